// round 1
// baseline (speedup 1.0000x reference)
#include <cuda_runtime.h>
#include <math.h>

// Problem constants
#define L_SEQ   2048
#define BATCH   16
#define N_IN    1024
#define N_OUT   1024
#define M_ROWS  (L_SEQ * BATCH)      // 32768
#define N_COLS  (2 * N_OUT)          // 2048
#define K_DIM   N_IN                 // 1024

// Output layout in d_out (fp32):
//   [0, M_ROWS*N_OUT)                      : cs   (also used as u0 scratch)
//   [M_ROWS*N_OUT, +BATCH*N_OUT)           : c_final
//   [M_ROWS*N_OUT+BATCH*N_OUT, +M_ROWS*N_OUT) : forget
#define CS_OFF      0
#define CFINAL_OFF  (M_ROWS * N_OUT)
#define FORGET_OFF  (M_ROWS * N_OUT + BATCH * N_OUT)

// ---------------------------------------------------------------------------
// GEMM + gate epilogue.
// C[row, col] = sum_k A[row,k] * W[k,col], row in [0,32768), col in [0,2048).
// Epilogue: for each o, col_even = 2o, col_odd = 2o+1:
//   f  = sigmoid(C[row,2o+1] + bias[1024+o])
//   u0 = C[row,2o] * (1 - f)
// Writes f -> forget region, u0 -> cs region.
// Block tile 64x64, BK=16, 256 threads, 4x4 per-thread tile.
// ---------------------------------------------------------------------------
#define BM 64
#define BN 64
#define BK 16
#define TM 4
#define TN 4

__global__ __launch_bounds__(256, 4)
void gemm_gate_kernel(const float* __restrict__ A,    // [32768, 1024]
                      const float* __restrict__ W,    // [1024, 2048]
                      const float* __restrict__ bias, // [2048]
                      float* __restrict__ u0_out,     // cs region
                      float* __restrict__ f_out)      // forget region
{
    __shared__ float As[BK][BM];      // transposed A tile
    __shared__ float Bs[BK][BN];

    const int tid = threadIdx.x;            // 0..255
    const int tx  = tid & 15;                // 0..15 -> N
    const int ty  = tid >> 4;                // 0..15 -> M

    const int rowBase = blockIdx.y * BM;     // M offset
    const int colBase = blockIdx.x * BN;     // N offset

    // A load mapping: each thread loads one float4: row = tid/4, kcol = (tid%4)*4
    const int aRow = tid >> 2;               // 0..63
    const int aK4  = (tid & 3) << 2;         // 0,4,8,12
    // B load mapping: each thread loads one float4: krow = tid/16, col = (tid%16)*4
    const int bK   = tid >> 4;               // 0..15
    const int bC4  = (tid & 15) << 2;        // 0..60

    float acc[TM][TN];
#pragma unroll
    for (int i = 0; i < TM; i++)
#pragma unroll
        for (int j = 0; j < TN; j++)
            acc[i][j] = 0.0f;

    const float* Aptr = A + (size_t)(rowBase + aRow) * K_DIM + aK4;
    const float* Wptr = W + (size_t)bK * N_COLS + colBase + bC4;

    for (int kt = 0; kt < K_DIM; kt += BK) {
        // load A tile (transposed into smem)
        float4 av = *reinterpret_cast<const float4*>(Aptr + kt);
        As[aK4 + 0][aRow] = av.x;
        As[aK4 + 1][aRow] = av.y;
        As[aK4 + 2][aRow] = av.z;
        As[aK4 + 3][aRow] = av.w;
        // load B tile
        float4 bv = *reinterpret_cast<const float4*>(Wptr + (size_t)kt * N_COLS);
        *reinterpret_cast<float4*>(&Bs[bK][bC4]) = bv;
        __syncthreads();

#pragma unroll
        for (int k = 0; k < BK; k++) {
            float am[TM], bn[TN];
            float4 a4 = *reinterpret_cast<const float4*>(&As[k][ty * TM]);
            am[0] = a4.x; am[1] = a4.y; am[2] = a4.z; am[3] = a4.w;
            float4 b4 = *reinterpret_cast<const float4*>(&Bs[k][tx * TN]);
            bn[0] = b4.x; bn[1] = b4.y; bn[2] = b4.z; bn[3] = b4.w;
#pragma unroll
            for (int i = 0; i < TM; i++)
#pragma unroll
                for (int j = 0; j < TN; j++)
                    acc[i][j] = fmaf(am[i], bn[j], acc[i][j]);
        }
        __syncthreads();
    }

    // Epilogue: each thread owns rows row0..row0+3, cols col0..col0+3
    const int row0 = rowBase + ty * TM;
    const int col0 = colBase + tx * TN;     // multiple of 4 -> pairs aligned
    const int o0   = col0 >> 1;             // first gate index (covers o0, o0+1)

    const float fb0 = bias[N_OUT + o0];
    const float fb1 = bias[N_OUT + o0 + 1];

#pragma unroll
    for (int i = 0; i < TM; i++) {
        const int row = row0 + i;
        // pair 0: cols col0 (even), col0+1 (odd)
        float f0 = 1.0f / (1.0f + __expf(-(acc[i][1] + fb0)));
        float u0 = acc[i][0] * (1.0f - f0);
        // pair 1: cols col0+2, col0+3
        float f1 = 1.0f / (1.0f + __expf(-(acc[i][3] + fb1)));
        float u1 = acc[i][2] * (1.0f - f1);

        float* fo = f_out  + (size_t)row * N_OUT + o0;
        float* uo = u0_out + (size_t)row * N_OUT + o0;
        fo[0] = f0; fo[1] = f1;
        uo[0] = u0; uo[1] = u1;
    }
}

// ---------------------------------------------------------------------------
// Sequential scan: c_t = c_{t-1} * f_t + u0_t, per independent (b, o) chain.
// 16384 chains, one thread each. u0 read from cs region, cs written in place.
// ---------------------------------------------------------------------------
__global__ __launch_bounds__(256)
void scan_kernel(const float* __restrict__ c_init,   // [16384]
                 float* __restrict__ cs,             // in: u0, out: cs
                 const float* __restrict__ f,        // forget
                 float* __restrict__ c_final)        // [16384]
{
    const int chain = blockIdx.x * blockDim.x + threadIdx.x;  // 0..16383
    float c = c_init[chain];
    size_t idx = chain;
#pragma unroll 8
    for (int l = 0; l < L_SEQ; l++) {
        float ft = f[idx];
        float u  = cs[idx];
        c = fmaf(c, ft, u);
        cs[idx] = c;
        idx += (size_t)BATCH * N_OUT;
    }
    c_final[chain] = c;
}

// ---------------------------------------------------------------------------
extern "C" void kernel_launch(void* const* d_in, const int* in_sizes, int n_in,
                              void* d_out, int out_size)
{
    const float* input  = (const float*)d_in[0];  // [2048,16,1024]
    const float* c_init = (const float*)d_in[1];  // [16,1024]
    const float* weight = (const float*)d_in[2];  // [1024,2048]
    const float* bias   = (const float*)d_in[3];  // [2048]

    float* out    = (float*)d_out;
    float* cs     = out + CS_OFF;
    float* cfin   = out + CFINAL_OFF;
    float* forget = out + FORGET_OFF;

    dim3 gemm_grid(N_COLS / BN, M_ROWS / BM);   // (32, 512)
    gemm_gate_kernel<<<gemm_grid, 256>>>(input, weight, bias, cs, forget);

    scan_kernel<<<(BATCH * N_OUT) / 256, 256>>>(c_init, cs, forget, cfin);
}

// round 3
// speedup vs baseline: 3.1508x; 3.1508x over previous
#include <cuda_runtime.h>
#include <cuda_bf16.h>
#include <stdint.h>

#define L_SEQ   2048
#define BATCH   16
#define N_IN    1024
#define N_OUT   1024
#define M_ROWS  (L_SEQ * BATCH)      // 32768
#define N_COLS  (2 * N_OUT)          // 2048
#define K_DIM   1024

#define CS_OFF      0
#define CFINAL_OFF  (M_ROWS * N_OUT)
#define FORGET_OFF  (M_ROWS * N_OUT + BATCH * N_OUT)

// bf16 hi/lo splits. A: [32768,1024] k-contig. B = W^T: [2048,1024] k-contig.
__device__ __nv_bfloat16 g_Ahi[(size_t)M_ROWS * K_DIM];
__device__ __nv_bfloat16 g_Alo[(size_t)M_ROWS * K_DIM];
__device__ __nv_bfloat16 g_Bhi[(size_t)N_COLS * K_DIM];
__device__ __nv_bfloat16 g_Blo[(size_t)N_COLS * K_DIM];

// ---------------------------------------------------------------------------
__device__ __forceinline__ uint32_t s2u(const void* p) {
    uint32_t r;
    asm("{ .reg .u64 t; cvta.to.shared.u64 t, %1; cvt.u32.u64 %0, t; }"
        : "=r"(r) : "l"(p));
    return r;
}
__device__ __forceinline__ void cp16(uint32_t saddr, const void* gptr) {
    uint64_t g = (uint64_t)__cvta_generic_to_global(gptr);
    asm volatile("cp.async.cg.shared.global [%0], [%1], 16;"
                 :: "r"(saddr), "l"(g) : "memory");
}
__device__ __forceinline__ void cp_commit() {
    asm volatile("cp.async.commit_group;" ::: "memory");
}
template <int N>
__device__ __forceinline__ void cp_wait() {
    asm volatile("cp.async.wait_group %0;" :: "n"(N) : "memory");
}
__device__ __forceinline__ void ldsm4(uint32_t* r, uint32_t addr) {
    asm volatile("ldmatrix.sync.aligned.m8n8.x4.shared.b16 {%0,%1,%2,%3}, [%4];"
                 : "=r"(r[0]), "=r"(r[1]), "=r"(r[2]), "=r"(r[3]) : "r"(addr));
}
__device__ __forceinline__ void mma16816(float* d, const uint32_t* a, const uint32_t* b) {
    asm volatile(
        "mma.sync.aligned.m16n8k16.row.col.f32.bf16.bf16.f32 "
        "{%0,%1,%2,%3}, {%4,%5,%6,%7}, {%8,%9}, {%0,%1,%2,%3};"
        : "+f"(d[0]), "+f"(d[1]), "+f"(d[2]), "+f"(d[3])
        : "r"(a[0]), "r"(a[1]), "r"(a[2]), "r"(a[3]), "r"(b[0]), "r"(b[1]));
}
__device__ __forceinline__ uint32_t swz(uint32_t off) {
    return off ^ ((off >> 3) & 0x70);
}

// ---------------------------------------------------------------------------
// Split kernels
// ---------------------------------------------------------------------------
__global__ __launch_bounds__(256)
void split_a_kernel(const float* __restrict__ A) {
    size_t i = ((size_t)blockIdx.x * 256 + threadIdx.x) * 4;
    float4 v = *reinterpret_cast<const float4*>(A + i);
    __nv_bfloat16 h0 = __float2bfloat16(v.x), h1 = __float2bfloat16(v.y);
    __nv_bfloat16 h2 = __float2bfloat16(v.z), h3 = __float2bfloat16(v.w);
    __nv_bfloat16 l0 = __float2bfloat16(v.x - __bfloat162float(h0));
    __nv_bfloat16 l1 = __float2bfloat16(v.y - __bfloat162float(h1));
    __nv_bfloat16 l2 = __float2bfloat16(v.z - __bfloat162float(h2));
    __nv_bfloat16 l3 = __float2bfloat16(v.w - __bfloat162float(h3));
    __nv_bfloat162* ph = reinterpret_cast<__nv_bfloat162*>(g_Ahi + i);
    __nv_bfloat162* pl = reinterpret_cast<__nv_bfloat162*>(g_Alo + i);
    ph[0] = __nv_bfloat162(h0, h1); ph[1] = __nv_bfloat162(h2, h3);
    pl[0] = __nv_bfloat162(l0, l1); pl[1] = __nv_bfloat162(l2, l3);
}

__global__ __launch_bounds__(256)
void split_w_kernel(const float* __restrict__ W) {
    __shared__ float t[32][33];
    int n0 = blockIdx.x * 32;
    int k0 = blockIdx.y * 32;
    int tx = threadIdx.x & 31;
    int ty = threadIdx.x >> 5;
#pragma unroll
    for (int i = 0; i < 4; i++)
        t[ty + i * 8][tx] = W[(size_t)(k0 + ty + i * 8) * N_COLS + n0 + tx];
    __syncthreads();
#pragma unroll
    for (int i = 0; i < 4; i++) {
        int n = ty + i * 8;
        float v = t[tx][n];
        __nv_bfloat16 h = __float2bfloat16(v);
        __nv_bfloat16 l = __float2bfloat16(v - __bfloat162float(h));
        size_t o = (size_t)(n0 + n) * K_DIM + k0 + tx;
        g_Bhi[o] = h;
        g_Blo[o] = l;
    }
}

// ---------------------------------------------------------------------------
// Tensor-core GEMM (mma.sync bf16 hi/lo, fp32 acc) + gate epilogue.
// BM=128, BN=128, BK=64, 256 threads = 8 warps (4M x 2N), warp tile 32x64.
// ---------------------------------------------------------------------------
#define BK 64
#define STAGE_BYTES 65536
#define OFF_AHI 0
#define OFF_ALO 16384
#define OFF_BHI 32768
#define OFF_BLO 49152
#define SMEM_TOTAL (2 * STAGE_BYTES)   // 131072
#define NCHUNK (K_DIM / BK)            // 16

__device__ __forceinline__ void load_stage(uint32_t sbase, int tid,
                                           int rowBase, int colBase, int k0) {
    const char* ahi = reinterpret_cast<const char*>(g_Ahi);
    const char* alo = reinterpret_cast<const char*>(g_Alo);
    const char* bhi = reinterpret_cast<const char*>(g_Bhi);
    const char* blo = reinterpret_cast<const char*>(g_Blo);
#pragma unroll
    for (int i = 0; i < 4; i++) {
        int idx = i * 256 + tid;            // 0..1023
        int row = idx >> 3, c = idx & 7;    // row 0..127, c*16 bytes
        uint32_t so = swz((uint32_t)(row * 128 + c * 16));
        size_t goA = ((size_t)(rowBase + row) * K_DIM + k0) * 2 + c * 16;
        size_t goB = ((size_t)(colBase + row) * K_DIM + k0) * 2 + c * 16;
        cp16(sbase + OFF_AHI + so, ahi + goA);
        cp16(sbase + OFF_ALO + so, alo + goA);
        cp16(sbase + OFF_BHI + so, bhi + goB);
        cp16(sbase + OFF_BLO + so, blo + goB);
    }
    cp_commit();
}

__global__ __launch_bounds__(256, 1)
void gemm_mma_kernel(const float* __restrict__ bias,
                     float* __restrict__ u0_out,
                     float* __restrict__ f_out) {
    extern __shared__ char smem[];
    const uint32_t sb = s2u(smem);
    const int tid = threadIdx.x;
    const int lid = tid & 31;
    const int wid = tid >> 5;
    const int warpM = wid & 3;          // 0..3 -> 32-row slice
    const int warpN = wid >> 2;         // 0..1 -> 64-col slice
    const int colBase = blockIdx.x * 128;
    const int rowBase = blockIdx.y * 128;

    float acc[2][8][4];
#pragma unroll
    for (int mi = 0; mi < 2; mi++)
#pragma unroll
        for (int ni = 0; ni < 8; ni++)
#pragma unroll
            for (int e = 0; e < 4; e++)
                acc[mi][ni][e] = 0.0f;

    const uint32_t st0 = sb;
    const uint32_t st1 = sb + STAGE_BYTES;

    load_stage(st0, tid, rowBase, colBase, 0);
    load_stage(st1, tid, rowBase, colBase, BK);

    // precompute intra-tile ldmatrix offsets (byte offsets before stage base)
    // A: row = warpM*32 + mi*16 + (lid&15), k byte = (kb + (lid>>4)*8)*2
    const int aRowIn = warpM * 32 + (lid & 15);
    const int aKIn   = (lid >> 4) * 8;
    // B: row = warpN*64 + nt*16 + (lid&7) + ((lid>>4)&1)*8 ; k = kb + ((lid>>3)&1)*8
    const int bRowIn = warpN * 64 + (lid & 7) + ((lid >> 4) & 1) * 8;
    const int bKIn   = ((lid >> 3) & 1) * 8;

    for (int c = 0; c < NCHUNK; c++) {
        if (c < NCHUNK - 1) cp_wait<1>(); else cp_wait<0>();
        __syncthreads();

        const uint32_t sbase = (c & 1) ? st1 : st0;
        const uint32_t aHi = sbase + OFF_AHI;
        const uint32_t aLo = sbase + OFF_ALO;
        const uint32_t bHi = sbase + OFF_BHI;
        const uint32_t bLo = sbase + OFF_BLO;

#pragma unroll
        for (int ks = 0; ks < 4; ks++) {
            const int kb = ks * 16;
            uint32_t ah[2][4], al[2][4];
#pragma unroll
            for (int mi = 0; mi < 2; mi++) {
                uint32_t off = swz((uint32_t)((aRowIn + mi * 16) * 128 +
                                              (kb + aKIn) * 2));
                ldsm4(ah[mi], aHi + off);
                ldsm4(al[mi], aLo + off);
            }
            uint32_t bh[8][2], bl[8][2];
#pragma unroll
            for (int nt = 0; nt < 4; nt++) {
                uint32_t off = swz((uint32_t)((bRowIn + nt * 16) * 128 +
                                              (kb + bKIn) * 2));
                uint32_t r[4];
                ldsm4(r, bHi + off);
                bh[nt * 2][0] = r[0]; bh[nt * 2][1] = r[1];
                bh[nt * 2 + 1][0] = r[2]; bh[nt * 2 + 1][1] = r[3];
                ldsm4(r, bLo + off);
                bl[nt * 2][0] = r[0]; bl[nt * 2][1] = r[1];
                bl[nt * 2 + 1][0] = r[2]; bl[nt * 2 + 1][1] = r[3];
            }
#pragma unroll
            for (int mi = 0; mi < 2; mi++)
#pragma unroll
                for (int ni = 0; ni < 8; ni++) {
                    mma16816(acc[mi][ni], ah[mi], bh[ni]);
                    mma16816(acc[mi][ni], ah[mi], bl[ni]);
                    mma16816(acc[mi][ni], al[mi], bh[ni]);
                }
        }

        __syncthreads();
        if (c + 2 < NCHUNK)
            load_stage(sbase, tid, rowBase, colBase, (c + 2) * BK);
    }

    // ------------- epilogue: gates + store -------------
    // C fragment: lane holds rows {r, r+8} at cols {2c, 2c+1} within each tile,
    // where r = lid/4, c = lid%4. Cols (2c,2c+1) = one gate pair.
    const int rBase = rowBase + warpM * 32 + (lid >> 2);
    const int oLane = (lid & 3);   // gate index offset within 8-col tile: o = .. + oLane

#pragma unroll
    for (int mi = 0; mi < 2; mi++) {
#pragma unroll
        for (int ni = 0; ni < 8; ni++) {
            const int o = ((colBase + warpN * 64 + ni * 8) >> 1) + oLane;
            const float fb = __ldg(bias + N_OUT + o);
            const int r0 = rBase + mi * 16;
            const int r1 = r0 + 8;
            // row r0: c0 (even col), c1 (odd col)
            float f0 = 1.0f / (1.0f + __expf(-(acc[mi][ni][1] + fb)));
            float u0 = acc[mi][ni][0] * (1.0f - f0);
            // row r1: c2, c3
            float f1 = 1.0f / (1.0f + __expf(-(acc[mi][ni][3] + fb)));
            float u1 = acc[mi][ni][2] * (1.0f - f1);
            u0_out[(size_t)r0 * N_OUT + o] = u0;
            f_out [(size_t)r0 * N_OUT + o] = f0;
            u0_out[(size_t)r1 * N_OUT + o] = u1;
            f_out [(size_t)r1 * N_OUT + o] = f1;
        }
    }
}

// ---------------------------------------------------------------------------
// Sequential scan: one thread per (b, o) chain.
// ---------------------------------------------------------------------------
__global__ __launch_bounds__(128)
void scan_kernel(const float* __restrict__ c_init,
                 float* __restrict__ cs,
                 const float* __restrict__ f,
                 float* __restrict__ c_final) {
    const int chain = blockIdx.x * blockDim.x + threadIdx.x;
    float c = c_init[chain];
    size_t idx = chain;
#pragma unroll 8
    for (int l = 0; l < L_SEQ; l++) {
        float ft = f[idx];
        float u  = cs[idx];
        c = fmaf(c, ft, u);
        cs[idx] = c;
        idx += (size_t)BATCH * N_OUT;
    }
    c_final[chain] = c;
}

// ---------------------------------------------------------------------------
extern "C" void kernel_launch(void* const* d_in, const int* in_sizes, int n_in,
                              void* d_out, int out_size)
{
    const float* input  = (const float*)d_in[0];
    const float* c_init = (const float*)d_in[1];
    const float* weight = (const float*)d_in[2];
    const float* bias   = (const float*)d_in[3];

    float* out    = (float*)d_out;
    float* cs     = out + CS_OFF;
    float* cfin   = out + CFINAL_OFF;
    float* forget = out + FORGET_OFF;

    cudaFuncSetAttribute(gemm_mma_kernel,
                         cudaFuncAttributeMaxDynamicSharedMemorySize, SMEM_TOTAL);

    split_a_kernel<<<(M_ROWS * K_DIM) / (256 * 4), 256>>>(input);
    split_w_kernel<<<dim3(N_COLS / 32, K_DIM / 32), 256>>>(weight);

    dim3 grid(N_COLS / 128, M_ROWS / 128);   // (16, 256)
    gemm_mma_kernel<<<grid, 256, SMEM_TOTAL>>>(bias, cs, forget);

    scan_kernel<<<(BATCH * N_OUT) / 128, 128>>>(c_init, cs, forget, cfin);
}

// round 4
// speedup vs baseline: 4.6783x; 1.4848x over previous
#include <cuda_runtime.h>
#include <cuda_fp16.h>
#include <stdint.h>

#define L_SEQ   2048
#define BATCH   16
#define N_IN    1024
#define N_OUT   1024
#define M_ROWS  (L_SEQ * BATCH)      // 32768
#define N_COLS  (2 * N_OUT)          // 2048
#define K_DIM   1024
#define NCH     (BATCH * N_OUT)      // 16384 chains

#define CS_OFF      0
#define CFINAL_OFF  (M_ROWS * N_OUT)
#define FORGET_OFF  (M_ROWS * N_OUT + BATCH * N_OUT)

// fp16 operands. A hi/lo: [32768,1024] k-contig. B = fp16(W^T): [2048,1024].
__device__ __half g_Ahi[(size_t)M_ROWS * K_DIM];
__device__ __half g_Alo[(size_t)M_ROWS * K_DIM];
__device__ __half g_Bh [(size_t)N_COLS * K_DIM];

// scan scratch
#define SEGS 16
#define SEG_LEN (L_SEQ / SEGS)       // 128
__device__ float g_F  [SEGS][NCH];
__device__ float g_U  [SEGS][NCH];
__device__ float g_Cin[SEGS][NCH];

// ---------------------------------------------------------------------------
__device__ __forceinline__ uint32_t s2u(const void* p) {
    uint32_t r;
    asm("{ .reg .u64 t; cvta.to.shared.u64 t, %1; cvt.u32.u64 %0, t; }"
        : "=r"(r) : "l"(p));
    return r;
}
__device__ __forceinline__ void cp16(uint32_t saddr, const void* gptr) {
    uint64_t g = (uint64_t)__cvta_generic_to_global(gptr);
    asm volatile("cp.async.cg.shared.global [%0], [%1], 16;"
                 :: "r"(saddr), "l"(g) : "memory");
}
__device__ __forceinline__ void cp_commit() {
    asm volatile("cp.async.commit_group;" ::: "memory");
}
template <int N>
__device__ __forceinline__ void cp_wait() {
    asm volatile("cp.async.wait_group %0;" :: "n"(N) : "memory");
}
__device__ __forceinline__ void ldsm4(uint32_t* r, uint32_t addr) {
    asm volatile("ldmatrix.sync.aligned.m8n8.x4.shared.b16 {%0,%1,%2,%3}, [%4];"
                 : "=r"(r[0]), "=r"(r[1]), "=r"(r[2]), "=r"(r[3]) : "r"(addr));
}
__device__ __forceinline__ void mma16816(float* d, const uint32_t* a, const uint32_t* b) {
    asm volatile(
        "mma.sync.aligned.m16n8k16.row.col.f32.f16.f16.f32 "
        "{%0,%1,%2,%3}, {%4,%5,%6,%7}, {%8,%9}, {%0,%1,%2,%3};"
        : "+f"(d[0]), "+f"(d[1]), "+f"(d[2]), "+f"(d[3])
        : "r"(a[0]), "r"(a[1]), "r"(a[2]), "r"(a[3]), "r"(b[0]), "r"(b[1]));
}
__device__ __forceinline__ uint32_t swz(uint32_t off) {
    return off ^ ((off >> 3) & 0x70);
}

// ---------------------------------------------------------------------------
// Operand prep
// ---------------------------------------------------------------------------
__global__ __launch_bounds__(256)
void convert_a_kernel(const float* __restrict__ A) {
    size_t i = ((size_t)blockIdx.x * 256 + threadIdx.x) * 4;
    float4 v = *reinterpret_cast<const float4*>(A + i);
    __half h0 = __float2half_rn(v.x), h1 = __float2half_rn(v.y);
    __half h2 = __float2half_rn(v.z), h3 = __float2half_rn(v.w);
    __half l0 = __float2half_rn(v.x - __half2float(h0));
    __half l1 = __float2half_rn(v.y - __half2float(h1));
    __half l2 = __float2half_rn(v.z - __half2float(h2));
    __half l3 = __float2half_rn(v.w - __half2float(h3));
    __half2* ph = reinterpret_cast<__half2*>(g_Ahi + i);
    __half2* pl = reinterpret_cast<__half2*>(g_Alo + i);
    ph[0] = __halves2half2(h0, h1); ph[1] = __halves2half2(h2, h3);
    pl[0] = __halves2half2(l0, l1); pl[1] = __halves2half2(l2, l3);
}

__global__ __launch_bounds__(256)
void convert_b_kernel(const float* __restrict__ W) {
    __shared__ float t[32][33];
    int n0 = blockIdx.x * 32;
    int k0 = blockIdx.y * 32;
    int tx = threadIdx.x & 31;
    int ty = threadIdx.x >> 5;
#pragma unroll
    for (int i = 0; i < 4; i++)
        t[ty + i * 8][tx] = W[(size_t)(k0 + ty + i * 8) * N_COLS + n0 + tx];
    __syncthreads();
#pragma unroll
    for (int i = 0; i < 4; i++) {
        int n = ty + i * 8;
        g_Bh[(size_t)(n0 + n) * K_DIM + k0 + tx] = __float2half_rn(t[tx][n]);
    }
}

// ---------------------------------------------------------------------------
// GEMM: BM=128, BN=64, BK=64, 256 threads (8 warps: 4M x 2N, warp tile 32x32).
// C = (Ahi + Alo) * Bh, fp32 accum. 2-stage cp.async pipeline.
// ---------------------------------------------------------------------------
#define BK 64
#define OFF_AHI 0
#define OFF_ALO 16384
#define OFF_BH  32768
#define STAGE_BYTES 40960
#define SMEM_TOTAL (2 * STAGE_BYTES)   // 81920
#define NCHUNK (K_DIM / BK)            // 16

__device__ __forceinline__ void load_stage(uint32_t sbase, int tid,
                                           int rowBase, int colBase, int k0) {
    const char* ahi = reinterpret_cast<const char*>(g_Ahi);
    const char* alo = reinterpret_cast<const char*>(g_Alo);
    const char* bh  = reinterpret_cast<const char*>(g_Bh);
#pragma unroll
    for (int i = 0; i < 4; i++) {               // A: 128 rows x 8 x 16B
        int idx = i * 256 + tid;
        int row = idx >> 3, c = idx & 7;
        uint32_t so = swz((uint32_t)(row * 128 + c * 16));
        size_t go = ((size_t)(rowBase + row) * K_DIM + k0) * 2 + c * 16;
        cp16(sbase + OFF_AHI + so, ahi + go);
        cp16(sbase + OFF_ALO + so, alo + go);
    }
#pragma unroll
    for (int i = 0; i < 2; i++) {               // B: 64 rows x 8 x 16B
        int idx = i * 256 + tid;
        int row = idx >> 3, c = idx & 7;
        uint32_t so = swz((uint32_t)(row * 128 + c * 16));
        size_t go = ((size_t)(colBase + row) * K_DIM + k0) * 2 + c * 16;
        cp16(sbase + OFF_BH + so, bh + go);
    }
    cp_commit();
}

__global__ __launch_bounds__(256, 2)
void gemm_mma_kernel(const float* __restrict__ bias,
                     float* __restrict__ u0_out,
                     float* __restrict__ f_out) {
    extern __shared__ char smem[];
    const uint32_t sb = s2u(smem);
    const int tid = threadIdx.x;
    const int lid = tid & 31;
    const int wid = tid >> 5;
    const int warpM = wid & 3;
    const int warpN = wid >> 2;          // 0..1
    const int colBase = blockIdx.x * 64;
    const int rowBase = blockIdx.y * 128;

    float acc[2][4][4];
#pragma unroll
    for (int mi = 0; mi < 2; mi++)
#pragma unroll
        for (int ni = 0; ni < 4; ni++)
#pragma unroll
            for (int e = 0; e < 4; e++)
                acc[mi][ni][e] = 0.0f;

    const uint32_t st0 = sb;
    const uint32_t st1 = sb + STAGE_BYTES;

    load_stage(st0, tid, rowBase, colBase, 0);
    load_stage(st1, tid, rowBase, colBase, BK);

    const int aRowIn = warpM * 32 + (lid & 15);
    const int aKIn   = (lid >> 4) * 8;
    const int bRowIn = warpN * 32 + (lid & 7) + ((lid >> 4) & 1) * 8;
    const int bKIn   = ((lid >> 3) & 1) * 8;

    for (int c = 0; c < NCHUNK; c++) {
        if (c < NCHUNK - 1) cp_wait<1>(); else cp_wait<0>();
        __syncthreads();

        const uint32_t sbase = (c & 1) ? st1 : st0;
        const uint32_t aHi = sbase + OFF_AHI;
        const uint32_t aLo = sbase + OFF_ALO;
        const uint32_t bHi = sbase + OFF_BH;

#pragma unroll
        for (int ks = 0; ks < 4; ks++) {
            const int kb = ks * 16;
            uint32_t ah[2][4], al[2][4];
#pragma unroll
            for (int mi = 0; mi < 2; mi++) {
                uint32_t off = swz((uint32_t)((aRowIn + mi * 16) * 128 +
                                              (kb + aKIn) * 2));
                ldsm4(ah[mi], aHi + off);
                ldsm4(al[mi], aLo + off);
            }
            uint32_t bh[4][2];
#pragma unroll
            for (int nt = 0; nt < 2; nt++) {
                uint32_t off = swz((uint32_t)((bRowIn + nt * 16) * 128 +
                                              (kb + bKIn) * 2));
                uint32_t r[4];
                ldsm4(r, bHi + off);
                bh[nt * 2][0] = r[0]; bh[nt * 2][1] = r[1];
                bh[nt * 2 + 1][0] = r[2]; bh[nt * 2 + 1][1] = r[3];
            }
#pragma unroll
            for (int mi = 0; mi < 2; mi++)
#pragma unroll
                for (int ni = 0; ni < 4; ni++) {
                    mma16816(acc[mi][ni], ah[mi], bh[ni]);
                    mma16816(acc[mi][ni], al[mi], bh[ni]);
                }
        }

        __syncthreads();
        if (c + 2 < NCHUNK)
            load_stage(sbase, tid, rowBase, colBase, (c + 2) * BK);
    }

    // epilogue: lane holds rows {r, r+8} cols {2c, 2c+1} per 16x8 tile
    const int rBase = rowBase + warpM * 32 + (lid >> 2);
    const int oLane = (lid & 3);

#pragma unroll
    for (int mi = 0; mi < 2; mi++) {
#pragma unroll
        for (int ni = 0; ni < 4; ni++) {
            const int o = ((colBase + warpN * 32 + ni * 8) >> 1) + oLane;
            const float fb = __ldg(bias + N_OUT + o);
            const int r0 = rBase + mi * 16;
            const int r1 = r0 + 8;
            float f0 = 1.0f / (1.0f + __expf(-(acc[mi][ni][1] + fb)));
            float u0 = acc[mi][ni][0] * (1.0f - f0);
            float f1 = 1.0f / (1.0f + __expf(-(acc[mi][ni][3] + fb)));
            float u1 = acc[mi][ni][2] * (1.0f - f1);
            u0_out[(size_t)r0 * N_OUT + o] = u0;
            f_out [(size_t)r0 * N_OUT + o] = f0;
            u0_out[(size_t)r1 * N_OUT + o] = u1;
            f_out [(size_t)r1 * N_OUT + o] = f1;
        }
    }
}

// ---------------------------------------------------------------------------
// Segmented scan (3 phases). Chains: j in [0,16384). Segments: 16 x 128 steps.
// ---------------------------------------------------------------------------
__global__ __launch_bounds__(256)
void scan_phaseA(const float* __restrict__ cs,      // u0 values
                 const float* __restrict__ f) {
    const int j = blockIdx.x * 256 + threadIdx.x;
    const int s = blockIdx.y;
    size_t idx = (size_t)s * SEG_LEN * NCH + j;
    float F = 1.0f, U = 0.0f;
#pragma unroll 8
    for (int t = 0; t < SEG_LEN; t++) {
        float ft = f[idx];
        float ut = cs[idx];
        U = fmaf(U, ft, ut);
        F *= ft;
        idx += NCH;
    }
    g_F[s][j] = F;
    g_U[s][j] = U;
}

__global__ __launch_bounds__(256)
void scan_phaseB(const float* __restrict__ c_init,
                 float* __restrict__ c_final) {
    const int j = blockIdx.x * 256 + threadIdx.x;
    float c = c_init[j];
#pragma unroll
    for (int s = 0; s < SEGS; s++) {
        g_Cin[s][j] = c;
        c = fmaf(c, g_F[s][j], g_U[s][j]);
    }
    c_final[j] = c;
}

__global__ __launch_bounds__(256)
void scan_phaseC(float* __restrict__ cs,
                 const float* __restrict__ f) {
    const int j = blockIdx.x * 256 + threadIdx.x;
    const int s = blockIdx.y;
    size_t idx = (size_t)s * SEG_LEN * NCH + j;
    float c = g_Cin[s][j];
#pragma unroll 8
    for (int t = 0; t < SEG_LEN; t++) {
        float ft = f[idx];
        float ut = cs[idx];
        c = fmaf(c, ft, ut);
        cs[idx] = c;
        idx += NCH;
    }
}

// ---------------------------------------------------------------------------
extern "C" void kernel_launch(void* const* d_in, const int* in_sizes, int n_in,
                              void* d_out, int out_size)
{
    const float* input  = (const float*)d_in[0];
    const float* c_init = (const float*)d_in[1];
    const float* weight = (const float*)d_in[2];
    const float* bias   = (const float*)d_in[3];

    float* out    = (float*)d_out;
    float* cs     = out + CS_OFF;
    float* cfin   = out + CFINAL_OFF;
    float* forget = out + FORGET_OFF;

    cudaFuncSetAttribute(gemm_mma_kernel,
                         cudaFuncAttributeMaxDynamicSharedMemorySize, SMEM_TOTAL);

    convert_a_kernel<<<(M_ROWS * K_DIM) / (256 * 4), 256>>>(input);
    convert_b_kernel<<<dim3(N_COLS / 32, K_DIM / 32), 256>>>(weight);

    dim3 grid(N_COLS / 64, M_ROWS / 128);   // (32, 256)
    gemm_mma_kernel<<<grid, 256, SMEM_TOTAL>>>(bias, cs, forget);

    dim3 sgrid(NCH / 256, SEGS);
    scan_phaseA<<<sgrid, 256>>>(cs, forget);
    scan_phaseB<<<NCH / 256, 256>>>(c_init, cfin);
    scan_phaseC<<<sgrid, 256>>>(cs, forget);
}

// round 5
// speedup vs baseline: 6.5257x; 1.3949x over previous
#include <cuda_runtime.h>
#include <cuda_fp16.h>
#include <stdint.h>

#define L_SEQ   2048
#define BATCH   16
#define N_IN    1024
#define N_OUT   1024
#define M_ROWS  (L_SEQ * BATCH)      // 32768
#define N_COLS  (2 * N_OUT)          // 2048
#define K_DIM   1024
#define NCH     (BATCH * N_OUT)      // 16384 chains

#define CS_OFF      0
#define CFINAL_OFF  (M_ROWS * N_OUT)
#define FORGET_OFF  (M_ROWS * N_OUT + BATCH * N_OUT)

// fp16 operands. A: [32768,1024] k-contig. B = fp16(W^T): [2048,1024].
__device__ __half g_Ah[(size_t)M_ROWS * K_DIM];
__device__ __half g_Bh[(size_t)N_COLS * K_DIM];

// scan scratch
#define SEGS 32
#define SEG_LEN (L_SEQ / SEGS)       // 64
__device__ float g_F  [SEGS][NCH];
__device__ float g_U  [SEGS][NCH];
__device__ float g_Cin[SEGS][NCH];

// ---------------------------------------------------------------------------
__device__ __forceinline__ uint32_t s2u(const void* p) {
    uint32_t r;
    asm("{ .reg .u64 t; cvta.to.shared.u64 t, %1; cvt.u32.u64 %0, t; }"
        : "=r"(r) : "l"(p));
    return r;
}
__device__ __forceinline__ void cp16(uint32_t saddr, const void* gptr) {
    uint64_t g = (uint64_t)__cvta_generic_to_global(gptr);
    asm volatile("cp.async.cg.shared.global [%0], [%1], 16;"
                 :: "r"(saddr), "l"(g) : "memory");
}
__device__ __forceinline__ void cp_commit() {
    asm volatile("cp.async.commit_group;" ::: "memory");
}
template <int N>
__device__ __forceinline__ void cp_wait() {
    asm volatile("cp.async.wait_group %0;" :: "n"(N) : "memory");
}
__device__ __forceinline__ void ldsm4(uint32_t* r, uint32_t addr) {
    asm volatile("ldmatrix.sync.aligned.m8n8.x4.shared.b16 {%0,%1,%2,%3}, [%4];"
                 : "=r"(r[0]), "=r"(r[1]), "=r"(r[2]), "=r"(r[3]) : "r"(addr));
}
__device__ __forceinline__ void mma16816(float* d, const uint32_t* a, const uint32_t* b) {
    asm volatile(
        "mma.sync.aligned.m16n8k16.row.col.f32.f16.f16.f32 "
        "{%0,%1,%2,%3}, {%4,%5,%6,%7}, {%8,%9}, {%0,%1,%2,%3};"
        : "+f"(d[0]), "+f"(d[1]), "+f"(d[2]), "+f"(d[3])
        : "r"(a[0]), "r"(a[1]), "r"(a[2]), "r"(a[3]), "r"(b[0]), "r"(b[1]));
}
__device__ __forceinline__ uint32_t swz(uint32_t off) {
    return off ^ ((off >> 3) & 0x70);
}

// ---------------------------------------------------------------------------
// Operand prep
// ---------------------------------------------------------------------------
__global__ __launch_bounds__(256)
void convert_a_kernel(const float* __restrict__ A) {
    size_t i = ((size_t)blockIdx.x * 256 + threadIdx.x) * 8;
    float4 v0 = *reinterpret_cast<const float4*>(A + i);
    float4 v1 = *reinterpret_cast<const float4*>(A + i + 4);
    __half2 h0 = __floats2half2_rn(v0.x, v0.y);
    __half2 h1 = __floats2half2_rn(v0.z, v0.w);
    __half2 h2 = __floats2half2_rn(v1.x, v1.y);
    __half2 h3 = __floats2half2_rn(v1.z, v1.w);
    uint4 pk;
    pk.x = *reinterpret_cast<uint32_t*>(&h0);
    pk.y = *reinterpret_cast<uint32_t*>(&h1);
    pk.z = *reinterpret_cast<uint32_t*>(&h2);
    pk.w = *reinterpret_cast<uint32_t*>(&h3);
    *reinterpret_cast<uint4*>(g_Ah + i) = pk;
}

__global__ __launch_bounds__(256)
void convert_b_kernel(const float* __restrict__ W) {
    __shared__ float t[32][33];
    int n0 = blockIdx.x * 32;
    int k0 = blockIdx.y * 32;
    int tx = threadIdx.x & 31;
    int ty = threadIdx.x >> 5;
#pragma unroll
    for (int i = 0; i < 4; i++)
        t[ty + i * 8][tx] = W[(size_t)(k0 + ty + i * 8) * N_COLS + n0 + tx];
    __syncthreads();
#pragma unroll
    for (int i = 0; i < 4; i++) {
        int n = ty + i * 8;
        g_Bh[(size_t)(n0 + n) * K_DIM + k0 + tx] = __float2half_rn(t[tx][n]);
    }
}

// ---------------------------------------------------------------------------
// GEMM: BM=256, BN=128, BK=64, 512 threads = 16 warps (4M x 4N),
// warp tile 64x32. C = Ah * Bh, fp32 accum. 2-stage cp.async pipeline.
// ---------------------------------------------------------------------------
#define BK 64
#define OFF_A 0
#define OFF_B 32768
#define STAGE_BYTES 49152
#define SMEM_TOTAL (2 * STAGE_BYTES)   // 98304
#define NCHUNK (K_DIM / BK)            // 16

__device__ __forceinline__ void load_stage(uint32_t sbase, int tid,
                                           int rowBase, int colBase, int k0) {
    const char* ah = reinterpret_cast<const char*>(g_Ah);
    const char* bh = reinterpret_cast<const char*>(g_Bh);
#pragma unroll
    for (int i = 0; i < 4; i++) {               // A: 256 rows x 8 x 16B
        int idx = i * 512 + tid;
        int row = idx >> 3, c = idx & 7;
        uint32_t so = swz((uint32_t)(row * 128 + c * 16));
        size_t go = ((size_t)(rowBase + row) * K_DIM + k0) * 2 + c * 16;
        cp16(sbase + OFF_A + so, ah + go);
    }
#pragma unroll
    for (int i = 0; i < 2; i++) {               // B: 128 rows x 8 x 16B
        int idx = i * 512 + tid;
        int row = idx >> 3, c = idx & 7;
        uint32_t so = swz((uint32_t)(row * 128 + c * 16));
        size_t go = ((size_t)(colBase + row) * K_DIM + k0) * 2 + c * 16;
        cp16(sbase + OFF_B + so, bh + go);
    }
    cp_commit();
}

__global__ __launch_bounds__(512, 1)
void gemm_mma_kernel(const float* __restrict__ bias,
                     float* __restrict__ u0_out,
                     float* __restrict__ f_out) {
    extern __shared__ char smem[];
    const uint32_t sb = s2u(smem);
    const int tid = threadIdx.x;
    const int lid = tid & 31;
    const int wid = tid >> 5;            // 0..15
    const int warpM = wid & 3;           // 4 x 64-row slices
    const int warpN = wid >> 2;          // 4 x 32-col slices
    const int colBase = blockIdx.x * 128;
    const int rowBase = blockIdx.y * 256;

    float acc[4][4][4];
#pragma unroll
    for (int mi = 0; mi < 4; mi++)
#pragma unroll
        for (int ni = 0; ni < 4; ni++)
#pragma unroll
            for (int e = 0; e < 4; e++)
                acc[mi][ni][e] = 0.0f;

    const uint32_t st0 = sb;
    const uint32_t st1 = sb + STAGE_BYTES;

    load_stage(st0, tid, rowBase, colBase, 0);
    load_stage(st1, tid, rowBase, colBase, BK);

    const int aRowIn = warpM * 64 + (lid & 15);
    const int aKIn   = (lid >> 4) * 8;
    const int bRowIn = warpN * 32 + (lid & 7) + ((lid >> 4) & 1) * 8;
    const int bKIn   = ((lid >> 3) & 1) * 8;

    for (int c = 0; c < NCHUNK; c++) {
        if (c < NCHUNK - 1) cp_wait<1>(); else cp_wait<0>();
        __syncthreads();

        const uint32_t sbase = (c & 1) ? st1 : st0;
        const uint32_t aS = sbase + OFF_A;
        const uint32_t bS = sbase + OFF_B;

#pragma unroll
        for (int ks = 0; ks < 4; ks++) {
            const int kb = ks * 16;
            uint32_t ah[4][4];
#pragma unroll
            for (int mi = 0; mi < 4; mi++) {
                uint32_t off = swz((uint32_t)((aRowIn + mi * 16) * 128 +
                                              (kb + aKIn) * 2));
                ldsm4(ah[mi], aS + off);
            }
            uint32_t bh[4][2];
#pragma unroll
            for (int nt = 0; nt < 2; nt++) {
                uint32_t off = swz((uint32_t)((bRowIn + nt * 16) * 128 +
                                              (kb + bKIn) * 2));
                uint32_t r[4];
                ldsm4(r, bS + off);
                bh[nt * 2][0] = r[0]; bh[nt * 2][1] = r[1];
                bh[nt * 2 + 1][0] = r[2]; bh[nt * 2 + 1][1] = r[3];
            }
#pragma unroll
            for (int mi = 0; mi < 4; mi++)
#pragma unroll
                for (int ni = 0; ni < 4; ni++)
                    mma16816(acc[mi][ni], ah[mi], bh[ni]);
        }

        __syncthreads();
        if (c + 2 < NCHUNK)
            load_stage(sbase, tid, rowBase, colBase, (c + 2) * BK);
    }

    // epilogue: lane holds rows {r, r+8} cols {2c, 2c+1} per 16x8 tile
    const int rBase = rowBase + warpM * 64 + (lid >> 2);
    const int oLane = (lid & 3);

#pragma unroll
    for (int mi = 0; mi < 4; mi++) {
#pragma unroll
        for (int ni = 0; ni < 4; ni++) {
            const int o = ((colBase + warpN * 32 + ni * 8) >> 1) + oLane;
            const float fb = __ldg(bias + N_OUT + o);
            const int r0 = rBase + mi * 16;
            const int r1 = r0 + 8;
            float f0 = 1.0f / (1.0f + __expf(-(acc[mi][ni][1] + fb)));
            float u0 = acc[mi][ni][0] * (1.0f - f0);
            float f1 = 1.0f / (1.0f + __expf(-(acc[mi][ni][3] + fb)));
            float u1 = acc[mi][ni][2] * (1.0f - f1);
            u0_out[(size_t)r0 * N_OUT + o] = u0;
            f_out [(size_t)r0 * N_OUT + o] = f0;
            u0_out[(size_t)r1 * N_OUT + o] = u1;
            f_out [(size_t)r1 * N_OUT + o] = f1;
        }
    }
}

// ---------------------------------------------------------------------------
// Segmented scan (3 phases). 32 segments x 64 steps.
// ---------------------------------------------------------------------------
__global__ __launch_bounds__(256)
void scan_phaseA(const float* __restrict__ cs,
                 const float* __restrict__ f) {
    const int j = blockIdx.x * 256 + threadIdx.x;
    const int s = blockIdx.y;
    size_t idx = (size_t)s * SEG_LEN * NCH + j;
    float F = 1.0f, U = 0.0f;
#pragma unroll 8
    for (int t = 0; t < SEG_LEN; t++) {
        float ft = f[idx];
        float ut = cs[idx];
        U = fmaf(U, ft, ut);
        F *= ft;
        idx += NCH;
    }
    g_F[s][j] = F;
    g_U[s][j] = U;
}

__global__ __launch_bounds__(256)
void scan_phaseB(const float* __restrict__ c_init,
                 float* __restrict__ c_final) {
    const int j = blockIdx.x * 256 + threadIdx.x;
    float c = c_init[j];
#pragma unroll
    for (int s = 0; s < SEGS; s++) {
        g_Cin[s][j] = c;
        c = fmaf(c, g_F[s][j], g_U[s][j]);
    }
    c_final[j] = c;
}

__global__ __launch_bounds__(256)
void scan_phaseC(float* __restrict__ cs,
                 const float* __restrict__ f) {
    const int j = blockIdx.x * 256 + threadIdx.x;
    const int s = blockIdx.y;
    size_t idx = (size_t)s * SEG_LEN * NCH + j;
    float c = g_Cin[s][j];
#pragma unroll 8
    for (int t = 0; t < SEG_LEN; t++) {
        float ft = f[idx];
        float ut = cs[idx];
        c = fmaf(c, ft, ut);
        cs[idx] = c;
        idx += NCH;
    }
}

// ---------------------------------------------------------------------------
extern "C" void kernel_launch(void* const* d_in, const int* in_sizes, int n_in,
                              void* d_out, int out_size)
{
    const float* input  = (const float*)d_in[0];
    const float* c_init = (const float*)d_in[1];
    const float* weight = (const float*)d_in[2];
    const float* bias   = (const float*)d_in[3];

    float* out    = (float*)d_out;
    float* cs     = out + CS_OFF;
    float* cfin   = out + CFINAL_OFF;
    float* forget = out + FORGET_OFF;

    cudaFuncSetAttribute(gemm_mma_kernel,
                         cudaFuncAttributeMaxDynamicSharedMemorySize, SMEM_TOTAL);

    convert_a_kernel<<<(M_ROWS * K_DIM) / (256 * 8), 256>>>(input);
    convert_b_kernel<<<dim3(N_COLS / 32, K_DIM / 32), 256>>>(weight);

    dim3 grid(N_COLS / 128, M_ROWS / 256);   // (16, 128)
    gemm_mma_kernel<<<grid, 512, SMEM_TOTAL>>>(bias, cs, forget);

    dim3 sgrid(NCH / 256, SEGS);
    scan_phaseA<<<sgrid, 256>>>(cs, forget);
    scan_phaseB<<<NCH / 256, 256>>>(c_init, cfin);
    scan_phaseC<<<sgrid, 256>>>(cs, forget);
}